// round 14
// baseline (speedup 1.0000x reference)
#include <cuda_runtime.h>

#define KA    9
#define HH    240
#define WW    240
#define HW    57600
#define NTOT  518400
#define WK    2160
#define PRE   6000
#define POST  300
#define CAP   8192
#define NB    65536
#define CHK   9
#define MROW  2048            // matrix-covered candidates
#define MW    64              // words per row (MROW/32)
#define NTHR  1024
#define MAXB  148

__device__ __align__(16) unsigned  g_hist[NB];    // zero invariant
__device__ unsigned                g_cnt;         // zero invariant
__device__ unsigned                g_rank[CAP];   // zero invariant
__device__ int                     g_bound;
__device__ unsigned long long      g_cand[CAP];
__device__ float                   g_sc[PRE];
__device__ float4                  g_boxes[PRE];
__device__ __align__(16) unsigned  g_mat[MROW * MW];
__device__ unsigned                g_bar_cnt;     // self-resetting
__device__ unsigned                g_bar_gen;     // monotone across launches

__device__ __forceinline__ unsigned mono(float f) {
    unsigned b = __float_as_uint(f);
    return (b & 0x80000000u) ? ~b : (b | 0x80000000u);
}
__device__ __forceinline__ float unmono(unsigned m) {
    unsigned b = (m & 0x80000000u) ? (m ^ 0x80000000u) : ~m;
    return __uint_as_float(b);
}
__device__ __forceinline__ float box_area(float4 b) {
    return __fmul_rn(fmaxf(b.z - b.x, 0.0f), fmaxf(b.w - b.y, 0.0f));
}
__device__ __forceinline__ bool iou_gt(float4 a, float areaA, float4 b, float areaB) {
    float lx = fmaxf(a.x, b.x);
    float ly = fmaxf(a.y, b.y);
    float rx = fminf(a.z, b.z);
    float ry = fminf(a.w, b.w);
    float iw = fmaxf(rx - lx, 0.0f);
    float ih = fmaxf(ry - ly, 0.0f);
    float inter = __fmul_rn(iw, ih);
    float uni = fmaxf(__fsub_rn(__fadd_rn(areaA, areaB), inter), 1e-9f);
    return __fdiv_rn(inter, uni) > 0.6f;
}
__device__ __forceinline__ bool iou_gt_eo(float4 a, float areaA, float4 b) {
    float lx = fmaxf(a.x, b.x);
    float ly = fmaxf(a.y, b.y);
    float rx = fminf(a.z, b.z);
    float ry = fminf(a.w, b.w);
    float iw = rx - lx;
    float ih = ry - ly;
    if (iw <= 0.0f || ih <= 0.0f) return false;
    float inter = __fmul_rn(iw, ih);
    float areaB = box_area(b);
    float uni = fmaxf(__fsub_rn(__fadd_rn(areaA, areaB), inter), 1e-9f);
    return __fdiv_rn(inter, uni) > 0.6f;
}
__device__ __forceinline__ void cp16(unsigned dst, const void* src) {
    asm volatile("cp.async.cg.shared.global [%0], [%1], 16;" :: "r"(dst), "l"(src));
}

// proven software grid barrier (R5-R7 lineage): grid <= #SMs => wave-1 resident
__device__ __forceinline__ void gsync(int nb) {
    __syncthreads();
    if (threadIdx.x == 0) {
        __threadfence();
        unsigned gen = *((volatile unsigned*)&g_bar_gen);
        unsigned t = atomicAdd(&g_bar_cnt, 1u);
        if (t == (unsigned)(nb - 1)) {
            atomicExch(&g_bar_cnt, 0u);
            __threadfence();
            atomicAdd(&g_bar_gen, 1u);
        } else {
            while (*((volatile unsigned*)&g_bar_gen) == gen) __nanosleep(64);
            __threadfence();
        }
    }
    __syncthreads();
}

__global__ __launch_bounds__(NTHR, 1)
void k_all(const float* __restrict__ cls,
           const float* __restrict__ deltas,
           const float* __restrict__ anchors,
           float* __restrict__ out, int nb) {
    __shared__ __align__(16) char smem_u[32 * MW * 4 * 4];   // 32 KB: rank sk / nms ring
    __shared__ int ws[32];
    const int tid = threadIdx.x;
    const int bid = blockIdx.x;
    const int lane = tid & 31, warp = tid >> 5;
    const int gt = bid * NTHR + tid;
    const int gs = nb * NTHR;

    // ---- P1: histogram (float4) -----------------------------------------
    for (int t = gt; t < NTOT / 4; t += gs) {
        int e = t * 4;
        int k = e / HW;
        int r = e - k * HW;
        const float4 v = *(const float4*)&cls[(2 * k) * HW + r];
        atomicAdd(&g_hist[mono(v.x) >> 16], 1u);
        atomicAdd(&g_hist[mono(v.y) >> 16], 1u);
        atomicAdd(&g_hist[mono(v.z) >> 16], 1u);
        atomicAdd(&g_hist[mono(v.w) >> 16], 1u);
    }
    gsync(nb);

    // ---- P2: boundary bucket (block 0) ----------------------------------
    if (bid == 0) {
        const uint4* h4 = (const uint4*)g_hist;
        int base4 = tid * 16;
        int sum = 0;
        #pragma unroll
        for (int j = 0; j < 16; ++j) {
            uint4 v = __ldcg(&h4[base4 + j]);
            sum += (int)(v.x + v.y + v.z + v.w);
        }
        int sfx = sum;
        #pragma unroll
        for (int d = 1; d < 32; d <<= 1) {
            int v = __shfl_down_sync(0xFFFFFFFFu, sfx, d);
            if (lane < 32 - d) sfx += v;
        }
        if (lane == 0) ws[warp] = sfx;
        __syncthreads();
        int tail = 0;
        for (int w2 = warp + 1; w2 < 32; ++w2) tail += ws[w2];
        int St  = sfx + tail;
        int Snx = St - sum;
        if (St >= PRE && Snx < PRE) {
            int running = Snx;
            int base = tid * 64;
            int B = base;
            for (int j = 63; j >= 0; --j) {
                running += (int)__ldcg(&g_hist[base + j]);
                if (running >= PRE) { B = base + j; break; }
            }
            g_bound = B;
        }
    }
    gsync(nb);

    // ---- P3: compact ------------------------------------------------------
    {
        const int bound = __ldcg(&g_bound);
        for (int i = gt; i < NTOT; i += gs) {
            int k = i / HW;
            int r = i - k * HW;
            unsigned key = mono(__ldg(&cls[(2 * k) * HW + r]));
            if ((int)(key >> 16) >= bound) {
                unsigned pos = atomicAdd(&g_cnt, 1u);
                if (pos < CAP)
                    g_cand[pos] = ((unsigned long long)key << 20)
                                | (unsigned)((~(unsigned)i) & 0xFFFFFu);
            }
        }
    }
    gsync(nb);

    // ---- P4: exact descending ranks by counting (144 tiles) --------------
    {
        unsigned long long* sk = (unsigned long long*)smem_u;
        unsigned n = __ldcg(&g_cnt); if (n > CAP) n = CAP;
        int csz = ((int)n + CHK - 1) / CHK;
        for (int w = bid; w < 16 * CHK; w += nb) {
            int g = w / CHK, c = w % CHK;
            int c0 = c * csz;
            int c1 = c0 + csz; if (c1 > (int)n) c1 = (int)n;
            int clen = c1 - c0;
            for (int j = tid; j < clen; j += NTHR) sk[j] = __ldcg(&g_cand[c0 + j]);
            __syncthreads();
            int ci = g * 512 + (tid & 511);
            int h  = tid >> 9;
            if (ci < (int)n && clen > 0) {
                unsigned long long my = __ldcg(&g_cand[ci]);
                int half = (clen + 1) >> 1;
                int j0 = h * half;
                int j1 = j0 + half; if (j1 > clen) j1 = clen;
                int cnt = 0;
                #pragma unroll 8
                for (int j = j0; j < j1; ++j) cnt += (sk[j] > my);
                if (cnt) atomicAdd(&g_rank[ci], (unsigned)cnt);
            }
            __syncthreads();
        }
    }
    gsync(nb);

    // ---- P5: scatter by rank + box decode — (candidate, corner) ----------
    {
        unsigned n = __ldcg(&g_cnt); if (n > CAP) n = CAP;
        for (int t = gt; t < (int)n * 4; t += gs) {
            int i = t >> 2, q = t & 3;
            unsigned r = __ldcg(&g_rank[i]);
            if (r >= PRE) continue;
            unsigned long long cv = __ldcg(&g_cand[i]);
            int idx = (int)((~(unsigned)cv) & 0xFFFFFu);
            if (q == 0) g_sc[r] = unmono((unsigned)(cv >> 20));
            int hp = idx / WK;
            int tt = idx - hp * WK;
            int wp = tt / KA;
            int kp = tt - wp * KA;
            int F   = ((kp * 4 + q) * HH + hp) * WW + wp;
            int j2  = F & 3;
            int F4  = F >> 2;
            int k2  = F4 % KA;
            int rem = F4 / KA;
            int w2  = rem % WW;
            int h2  = rem / WW;
            float a = __ldg(&anchors[((h2 * WW + w2) * KA + k2) * 4 + j2]);
            float d = __ldg(&deltas[(k2 * 4 + j2) * HW + h2 * WW + w2]);
            ((float*)&g_boxes[r])[q] = fminf(fmaxf(a + d, 0.0f), 1920.0f);
        }
    }
    gsync(nb);

    // ---- P6: upper-triangle suppression bit-matrix -----------------------
    for (int i = bid; i < MROW; i += nb) {
        float4 bi = __ldcg(&g_boxes[i]);
        float  ai = box_area(bi);
        int j0 = tid;
        int j1 = j0 + 1024;
        float4 b0 = __ldcg(&g_boxes[j0]);
        float4 b1 = __ldcg(&g_boxes[j1]);
        bool s0 = (j0 > i) && iou_gt_eo(bi, ai, b0);
        bool s1 = (j1 > i) && iou_gt_eo(bi, ai, b1);
        unsigned w0 = __ballot_sync(0xFFFFFFFFu, s0);
        unsigned w1 = __ballot_sync(0xFFFFFFFFu, s1);
        if ((j0 & 31) == 0) {
            int w = j0 >> 5;
            g_mat[i * MW + w]      = w0;
            g_mat[i * MW + w + 32] = w1;
        }
    }
    gsync(nb);

    // ---- P7: block 0 sweep + output; other blocks restore invariants -----
    if (bid != 0) {
        int gt2 = (bid - 1) * NTHR + tid;
        int gs2 = (nb - 1) * NTHR;
        for (int i = gt2; i < NB;  i += gs2) g_hist[i] = 0u;
        for (int i = gt2; i < CAP; i += gs2) g_rank[i] = 0u;
        if (bid == 1 && tid == 0) g_cnt = 0u;
        return;
    }

    __shared__ int      s_kidx[POST];
    __shared__ int      s_nk;
    __shared__ float4   kbox[POST];
    __shared__ float    karea[POST];
    __shared__ float4   bb[32];
    __shared__ float    ba[32];
    __shared__ unsigned s_sup;
    unsigned* rowbuf = (unsigned*)smem_u;             // 4 x 8 KB ring

    if (warp == 0) {
        unsigned sbase = (unsigned)__cvta_generic_to_shared(smem_u) + lane * 16;
        unsigned m0 = 0u, m1 = 0u;
        int nk = 0;
        #pragma unroll
        for (int p = 0; p < 3; ++p) {
            const uint4* src = (const uint4*)&g_mat[(p << 5) * MW];
            unsigned d = sbase + p * 8192;
            #pragma unroll
            for (int q = 0; q < 16; ++q) cp16(d + q * 512, src + lane + 32 * q);
            asm volatile("cp.async.commit_group;");
        }
        for (int c = 0; c < MW && nk < POST; ++c) {
            if (c + 3 < MW) {
                const uint4* src = (const uint4*)&g_mat[((c + 3) << 5) * MW];
                unsigned d = sbase + ((c + 3) & 3) * 8192;
                #pragma unroll
                for (int q = 0; q < 16; ++q) cp16(d + q * 512, src + lane + 32 * q);
            }
            asm volatile("cp.async.commit_group;");
            asm volatile("cp.async.wait_group 3;");
            __syncwarp();
            const unsigned* rb = rowbuf + (c & 3) * (32 * MW);
            unsigned cur = __shfl_sync(0xFFFFFFFFu, (c & 1) ? m1 : m0, c >> 1);
            unsigned alive = ~cur;
            while (alive && nk < POST) {
                int l = __ffs(alive) - 1;
                if (lane == 0) s_kidx[nk] = (c << 5) + l;
                ++nk;
                cur |= rb[l * MW + c];
                m0  |= rb[l * MW + 2 * lane];
                m1  |= rb[l * MW + 2 * lane + 1];
                alive = (~cur) & ~((2u << l) - 1u);
            }
            __syncwarp();
        }
        asm volatile("cp.async.wait_group 0;");
        if (lane == 0) s_nk = nk;
    }
    __syncthreads();
    int nk = s_nk;

    if (nk < POST) {                                  // rare fallback past MROW
        for (int p = tid; p < nk; p += NTHR) {
            float4 b = __ldcg(&g_boxes[s_kidx[p]]);
            kbox[p] = b; karea[p] = box_area(b);
        }
        if (tid == 0) s_sup = 0u;
        __syncthreads();
        for (int base = MROW; base < PRE && nk < POST; base += 32) {
            int rem = PRE - base; if (rem > 32) rem = 32;
            if (tid < rem) {
                float4 b = __ldcg(&g_boxes[base + tid]);
                bb[tid] = b; ba[tid] = box_area(b);
            }
            __syncthreads();
            int total = nk << 5;
            for (int idx2 = tid; idx2 < total; idx2 += NTHR) {
                int cc = idx2 & 31;
                if (cc < rem && !((s_sup >> cc) & 1u)) {
                    int k = idx2 >> 5;
                    if (iou_gt(kbox[k], karea[k], bb[cc], ba[cc]))
                        atomicOr(&s_sup, 1u << cc);
                }
            }
            __syncthreads();
            if (tid < 32) {
                unsigned valid = (rem >= 32) ? 0xFFFFFFFFu : ((1u << rem) - 1u);
                unsigned alive = (~s_sup) & valid;
                float4 myb = bb[(lane < rem) ? lane : 0];
                float  mya = ba[(lane < rem) ? lane : 0];
                int nk2 = nk;
                while (alive && nk2 < POST) {
                    int l = __ffs((int)alive) - 1;
                    alive &= ~(1u << l);
                    float4 kb;
                    kb.x = __shfl_sync(0xFFFFFFFFu, myb.x, l);
                    kb.y = __shfl_sync(0xFFFFFFFFu, myb.y, l);
                    kb.z = __shfl_sync(0xFFFFFFFFu, myb.z, l);
                    kb.w = __shfl_sync(0xFFFFFFFFu, myb.w, l);
                    float ka_ = __shfl_sync(0xFFFFFFFFu, mya, l);
                    if (lane == 0) { kbox[nk2] = kb; karea[nk2] = ka_; s_kidx[nk2] = base + l; }
                    ++nk2;
                    if (nk2 >= POST) break;
                    bool sup = false;
                    if (alive & (1u << lane)) sup = iou_gt(kb, ka_, myb, mya);
                    alive &= ~__ballot_sync(0xFFFFFFFFu, sup);
                }
                if (lane == 0) { s_nk = nk2; s_sup = 0u; }
            }
            __syncthreads();
            nk = s_nk;
        }
    }

    // output [1, POST, 5]; pad with candidate 0 (nonzero fill_value=0)
    for (int p = tid; p < POST; p += NTHR) {
        int q = (p < nk) ? s_kidx[p] : 0;
        float4 b = __ldcg(&g_boxes[q]);
        out[p * 5 + 0] = __ldcg(&g_sc[q]);
        out[p * 5 + 1] = b.x;
        out[p * 5 + 2] = b.y;
        out[p * 5 + 3] = b.z;
        out[p * 5 + 4] = b.w;
    }
}

// ---------------------------------------------------------------- launcher
extern "C" void kernel_launch(void* const* d_in, const int* in_sizes, int n_in,
                              void* d_out, int out_size) {
    const float* cls     = (const float*)d_in[0];
    const float* deltas  = (const float*)d_in[1];
    const float* anchors = (const float*)d_in[2];
    float* out = (float*)d_out;

    int smCount = MAXB;
    cudaDeviceGetAttribute(&smCount, cudaDevAttrMultiProcessorCount, 0);
    int nb = smCount < MAXB ? smCount : MAXB;

    k_all<<<nb, NTHR>>>(cls, deltas, anchors, out, nb);
}

// round 15
// speedup vs baseline: 1.1041x; 1.1041x over previous
#include <cuda_runtime.h>

#define KA    9
#define HH    240
#define WW    240
#define HW    57600
#define NTOT  518400
#define WK    2160
#define PRE   6000
#define POST  300
#define CAP   8192
#define NB    65536
#define CHK   9
#define MROW  2048            // matrix-covered candidates
#define MW    64              // words per row (MROW/32)

__device__ __align__(16) unsigned  g_hist[NB];    // zero invariant
__device__ unsigned                g_cnt;         // zero invariant
__device__ unsigned                g_rank[CAP];   // zero invariant
__device__ int                     g_bound;
__device__ unsigned long long      g_cand[CAP];
__device__ float                   g_sc[PRE];
__device__ float4                  g_boxes[PRE];
__device__ __align__(16) unsigned  g_mat[MROW * MW];

__device__ __forceinline__ unsigned mono(float f) {
    unsigned b = __float_as_uint(f);
    return (b & 0x80000000u) ? ~b : (b | 0x80000000u);
}
__device__ __forceinline__ float unmono(unsigned m) {
    unsigned b = (m & 0x80000000u) ? (m ^ 0x80000000u) : ~m;
    return __uint_as_float(b);
}
__device__ __forceinline__ float box_area(float4 b) {
    return __fmul_rn(fmaxf(b.z - b.x, 0.0f), fmaxf(b.w - b.y, 0.0f));
}
// exact formula (rel_err 0.0 lineage)
__device__ __forceinline__ bool iou_gt(float4 a, float areaA, float4 b, float areaB) {
    float lx = fmaxf(a.x, b.x);
    float ly = fmaxf(a.y, b.y);
    float rx = fminf(a.z, b.z);
    float ry = fminf(a.w, b.w);
    float iw = fmaxf(rx - lx, 0.0f);
    float ih = fmaxf(ry - ly, 0.0f);
    float inter = __fmul_rn(iw, ih);
    float uni = fmaxf(__fsub_rn(__fadd_rn(areaA, areaB), inter), 1e-9f);
    return __fdiv_rn(inter, uni) > 0.6f;
}
// early-out: iw<=0 or ih<=0 => inter=0 => IoU=0, never >0.6 (exact)
__device__ __forceinline__ bool iou_gt_eo(float4 a, float areaA, float4 b) {
    float lx = fmaxf(a.x, b.x);
    float ly = fmaxf(a.y, b.y);
    float rx = fminf(a.z, b.z);
    float ry = fminf(a.w, b.w);
    float iw = rx - lx;
    float ih = ry - ly;
    if (iw <= 0.0f || ih <= 0.0f) return false;
    float inter = __fmul_rn(iw, ih);
    float areaB = box_area(b);
    float uni = fmaxf(__fsub_rn(__fadd_rn(areaA, areaB), inter), 1e-9f);
    return __fdiv_rn(inter, uni) > 0.6f;
}
__device__ __forceinline__ void cp16(unsigned dst, const void* src) {
    asm volatile("cp.async.cg.shared.global [%0], [%1], 16;" :: "r"(dst), "l"(src));
}

// ---- 1: scores -> 64K-bucket histogram (float4) -------------------------
__global__ void k_hist(const float* __restrict__ cls) {
    int t = blockIdx.x * blockDim.x + threadIdx.x;
    if (t >= NTOT / 4) return;
    int e = t * 4;
    int k = e / HW;
    int r = e - k * HW;
    const float4 v = *(const float4*)&cls[(2 * k) * HW + r];
    atomicAdd(&g_hist[mono(v.x) >> 16], 1u);
    atomicAdd(&g_hist[mono(v.y) >> 16], 1u);
    atomicAdd(&g_hist[mono(v.z) >> 16], 1u);
    atomicAdd(&g_hist[mono(v.w) >> 16], 1u);
}

// ---- 2: boundary bucket of rank PRE -------------------------------------
__global__ __launch_bounds__(1024) void k_bound() {
    __shared__ int ws[32];
    int tid = threadIdx.x;
    const uint4* h4 = (const uint4*)g_hist;
    int base4 = tid * 16;
    int sum = 0;
    #pragma unroll
    for (int j = 0; j < 16; ++j) {
        uint4 v = h4[base4 + j];
        sum += (int)(v.x + v.y + v.z + v.w);
    }
    int lane = tid & 31, warp = tid >> 5;
    int sfx = sum;
    #pragma unroll
    for (int d = 1; d < 32; d <<= 1) {
        int v = __shfl_down_sync(0xFFFFFFFFu, sfx, d);
        if (lane < 32 - d) sfx += v;
    }
    if (lane == 0) ws[warp] = sfx;
    __syncthreads();
    int tail = 0;
    for (int w2 = warp + 1; w2 < 32; ++w2) tail += ws[w2];
    int St  = sfx + tail;
    int Snx = St - sum;
    if (St >= PRE && Snx < PRE) {
        int running = Snx;
        int base = tid * 64;
        int B = base;
        for (int j = 63; j >= 0; --j) {
            running += (int)g_hist[base + j];
            if (running >= PRE) { B = base + j; break; }
        }
        g_bound = B;
    }
}

// ---- 3: compact candidates >= bound -------------------------------------
__global__ void k_compact(const float* __restrict__ cls) {
    int i = blockIdx.x * blockDim.x + threadIdx.x;
    if (i >= NTOT) return;
    int k = i / HW;
    int r = i - k * HW;
    float s = __ldg(&cls[(2 * k) * HW + r]);
    unsigned key = mono(s);
    if ((int)(key >> 16) >= g_bound) {
        unsigned pos = atomicAdd(&g_cnt, 1u);
        if (pos < CAP)
            g_cand[pos] = ((unsigned long long)key << 20)
                        | (unsigned)((~(unsigned)i) & 0xFFFFFu);
    }
}

// ---- 4: ranks by counting — 4 candidates/thread, broadcast smem reads ----
__global__ __launch_bounds__(1024) void k_rank() {
    __shared__ unsigned long long sk[1024];
    unsigned n = g_cnt; if (n > CAP) n = CAP;
    int csz = ((int)n + CHK - 1) / CHK;
    int w = blockIdx.x;                  // 0..143 = 16 groups x 9 chunks
    int g = w / CHK, c = w % CHK;
    int c0 = c * csz;
    int c1 = c0 + csz; if (c1 > (int)n) c1 = (int)n;
    int clen = c1 - c0;
    for (int j = threadIdx.x; j < clen; j += 1024) sk[j] = g_cand[c0 + j];
    __syncthreads();
    if (clen <= 0) return;

    int quad = threadIdx.x & 127;        // 128 quads x 4 candidates = 512/group
    int s    = threadIdx.x >> 7;         // 8 sub-ranges (uniform per warp)
    int ci0  = g * 512 + quad * 4;
    unsigned long long k0 = (ci0 + 0 < (int)n) ? g_cand[ci0 + 0] : ~0ULL;
    unsigned long long k1 = (ci0 + 1 < (int)n) ? g_cand[ci0 + 1] : ~0ULL;
    unsigned long long k2 = (ci0 + 2 < (int)n) ? g_cand[ci0 + 2] : ~0ULL;
    unsigned long long k3 = (ci0 + 3 < (int)n) ? g_cand[ci0 + 3] : ~0ULL;
    int sub = (clen + 7) >> 3;
    int j0 = s * sub;
    int j1 = j0 + sub; if (j1 > clen) j1 = clen;
    int n0 = 0, n1 = 0, n2 = 0, n3 = 0;
    #pragma unroll 4
    for (int j = j0; j < j1; ++j) {
        unsigned long long kk = sk[j];   // broadcast: same j across all lanes
        n0 += (kk > k0);
        n1 += (kk > k1);
        n2 += (kk > k2);
        n3 += (kk > k3);
    }
    if (ci0 + 0 < (int)n && n0) atomicAdd(&g_rank[ci0 + 0], (unsigned)n0);
    if (ci0 + 1 < (int)n && n1) atomicAdd(&g_rank[ci0 + 1], (unsigned)n1);
    if (ci0 + 2 < (int)n && n2) atomicAdd(&g_rank[ci0 + 2], (unsigned)n2);
    if (ci0 + 3 < (int)n && n3) atomicAdd(&g_rank[ci0 + 3], (unsigned)n3);
}

// ---- 5: scatter by rank + box decode — (candidate, corner) threads -------
__global__ void k_scatter(const float* __restrict__ deltas,
                          const float* __restrict__ anchors) {
    int t = blockIdx.x * blockDim.x + threadIdx.x;
    int i = t >> 2, q = t & 3;
    unsigned n = g_cnt; if (n > CAP) n = CAP;
    if (i >= (int)n) return;
    unsigned r = g_rank[i];
    if (r >= PRE) return;
    unsigned long long cv = g_cand[i];
    int idx = (int)((~(unsigned)cv) & 0xFFFFFu);
    if (q == 0) g_sc[r] = unmono((unsigned)(cv >> 20));
    int hp = idx / WK;
    int tt = idx - hp * WK;
    int wp = tt / KA;
    int kp = tt - wp * KA;
    int F   = ((kp * 4 + q) * HH + hp) * WW + wp;
    int j2  = F & 3;
    int F4  = F >> 2;
    int k2  = F4 % KA;
    int rem = F4 / KA;
    int w2  = rem % WW;
    int h2  = rem / WW;
    float a = __ldg(&anchors[((h2 * WW + w2) * KA + k2) * 4 + j2]);
    float d = __ldg(&deltas[(k2 * 4 + j2) * HW + h2 * WW + w2]);
    ((float*)&g_boxes[r])[q] = fminf(fmaxf(a + d, 0.0f), 1920.0f);
}

// ---- 6: upper-triangle suppression bit-matrix + invariant resets ---------
__global__ __launch_bounds__(1024) void k_mat() {
    int i = blockIdx.x;
    int tid = threadIdx.x;
    float4 bi = g_boxes[i];
    float  ai = box_area(bi);
    int j0 = tid;
    int j1 = j0 + 1024;
    bool s0 = (j0 > i) && iou_gt_eo(bi, ai, g_boxes[j0]);
    bool s1 = (j1 > i) && iou_gt_eo(bi, ai, g_boxes[j1]);
    unsigned w0 = __ballot_sync(0xFFFFFFFFu, s0);
    unsigned w1 = __ballot_sync(0xFFFFFFFFu, s1);
    if ((j0 & 31) == 0) {
        int w = j0 >> 5;
        g_mat[i * MW + w]      = w0;
        g_mat[i * MW + w + 32] = w1;
    }
    // invariant resets on dead data: 2048 blocks x 32 = NB; x4 = CAP
    if (tid < 32)                      g_hist[i * 32 + tid] = 0u;
    else if (tid < 36)                 g_rank[i * 4 + (tid - 32)] = 0u;
    else if (tid == 36 && i == 0)      g_cnt = 0u;
}

// ---- 7: sweep — warp 1 produces (cp.async ring-8), warp 0 consumes -------
__global__ __launch_bounds__(1024) void k_nms(float* __restrict__ out) {
    extern __shared__ __align__(16) unsigned ring[];   // 8 x 8 KB dynamic
    __shared__ int      s_kidx[POST];
    __shared__ int      s_nk;
    __shared__ float4   kbox[POST];
    __shared__ float    karea[POST];
    __shared__ float4   bb[32];
    __shared__ float    ba[32];
    __shared__ unsigned s_sup;
    int tid = threadIdx.x, lane = tid & 31, warp = tid >> 5;

    if (warp == 1) {
        // producer: stay 6 chunks ahead; slot (c&7); handshake per chunk
        unsigned sbase = (unsigned)__cvta_generic_to_shared(ring) + lane * 16;
        #pragma unroll
        for (int p = 0; p < 6; ++p) {
            const uint4* src = (const uint4*)&g_mat[(p << 5) * MW];
            unsigned d = sbase + p * 8192;
            #pragma unroll
            for (int q = 0; q < 16; ++q) cp16(d + q * 512, src + lane + 32 * q);
            asm volatile("cp.async.commit_group;");
        }
        for (int c = 0; c < MW; ++c) {
            if (c + 6 < MW) {
                const uint4* src = (const uint4*)&g_mat[((c + 6) << 5) * MW];
                unsigned d = sbase + ((c + 6) & 7) * 8192;
                #pragma unroll
                for (int q = 0; q < 16; ++q) cp16(d + q * 512, src + lane + 32 * q);
            }
            asm volatile("cp.async.commit_group;");    // uniform group count
            asm volatile("cp.async.wait_group 6;");    // chunk c complete in smem
            asm volatile("bar.sync 1, 64;" ::: "memory");
        }
        asm volatile("cp.async.wait_group 0;");
    } else if (warp == 0) {
        unsigned m0 = 0u, m1 = 0u;     // lane owns future-mask words 2*lane, 2*lane+1
        int nk = 0;
        for (int c = 0; c < MW; ++c) {
            asm volatile("bar.sync 1, 64;" ::: "memory");   // chunk c ready
            if (nk >= POST) continue;                       // keep handshakes aligned
            const unsigned* rb = ring + (c & 7) * (32 * MW);
            unsigned cur = __shfl_sync(0xFFFFFFFFu, (c & 1) ? m1 : m0, c >> 1);
            unsigned alive = ~cur;
            while (alive && nk < POST) {
                int l = __ffs(alive) - 1;
                if (lane == 0) s_kidx[nk] = (c << 5) + l;
                ++nk;
                cur |= rb[l * MW + c];                 // broadcast LDS
                m0  |= rb[l * MW + 2 * lane];
                m1  |= rb[l * MW + 2 * lane + 1];
                alive = (~cur) & ~((2u << l) - 1u);    // unsuppressed, index > l
            }
        }
        if (lane == 0) s_nk = nk;
    }
    __syncthreads();
    int nk = s_nk;

    // fallback past MROW (rare): lazy 32-wide batches
    if (nk < POST) {
        for (int p = tid; p < nk; p += 1024) {
            float4 b = g_boxes[s_kidx[p]];
            kbox[p] = b; karea[p] = box_area(b);
        }
        if (tid == 0) s_sup = 0u;
        __syncthreads();
        for (int base = MROW; base < PRE && nk < POST; base += 32) {
            int rem = PRE - base; if (rem > 32) rem = 32;
            if (tid < rem) {
                float4 b = g_boxes[base + tid];
                bb[tid] = b; ba[tid] = box_area(b);
            }
            __syncthreads();
            int total = nk << 5;
            for (int idx2 = tid; idx2 < total; idx2 += 1024) {
                int cc = idx2 & 31;
                if (cc < rem && !((s_sup >> cc) & 1u)) {
                    int k = idx2 >> 5;
                    if (iou_gt(kbox[k], karea[k], bb[cc], ba[cc]))
                        atomicOr(&s_sup, 1u << cc);
                }
            }
            __syncthreads();
            if (tid < 32) {
                unsigned valid = (rem >= 32) ? 0xFFFFFFFFu : ((1u << rem) - 1u);
                unsigned alive = (~s_sup) & valid;
                float4 myb = bb[(lane < rem) ? lane : 0];
                float  mya = ba[(lane < rem) ? lane : 0];
                int nk2 = nk;
                while (alive && nk2 < POST) {
                    int l = __ffs((int)alive) - 1;
                    alive &= ~(1u << l);
                    float4 kb;
                    kb.x = __shfl_sync(0xFFFFFFFFu, myb.x, l);
                    kb.y = __shfl_sync(0xFFFFFFFFu, myb.y, l);
                    kb.z = __shfl_sync(0xFFFFFFFFu, myb.z, l);
                    kb.w = __shfl_sync(0xFFFFFFFFu, myb.w, l);
                    float ka_ = __shfl_sync(0xFFFFFFFFu, mya, l);
                    if (lane == 0) { kbox[nk2] = kb; karea[nk2] = ka_; s_kidx[nk2] = base + l; }
                    ++nk2;
                    if (nk2 >= POST) break;
                    bool sup = false;
                    if (alive & (1u << lane)) sup = iou_gt(kb, ka_, myb, mya);
                    alive &= ~__ballot_sync(0xFFFFFFFFu, sup);
                }
                if (lane == 0) { s_nk = nk2; s_sup = 0u; }
            }
            __syncthreads();
            nk = s_nk;
        }
    }

    // output [1, POST, 5]; pad with candidate 0 (nonzero fill_value=0)
    for (int p = tid; p < POST; p += 1024) {
        int q = (p < nk) ? s_kidx[p] : 0;
        float4 b = g_boxes[q];
        out[p * 5 + 0] = g_sc[q];
        out[p * 5 + 1] = b.x;
        out[p * 5 + 2] = b.y;
        out[p * 5 + 3] = b.z;
        out[p * 5 + 4] = b.w;
    }
}

// ---------------------------------------------------------------- launcher
extern "C" void kernel_launch(void* const* d_in, const int* in_sizes, int n_in,
                              void* d_out, int out_size) {
    const float* cls     = (const float*)d_in[0];
    const float* deltas  = (const float*)d_in[1];
    const float* anchors = (const float*)d_in[2];
    float* out = (float*)d_out;

    cudaFuncSetAttribute(k_nms, cudaFuncAttributeMaxDynamicSharedMemorySize,
                         8 * 32 * MW * 4);

    k_hist   <<<(NTOT / 4 + 255) / 256, 256>>>(cls);
    k_bound  <<<1, 1024>>>();
    k_compact<<<(NTOT + 255) / 256, 256>>>(cls);
    k_rank   <<<144, 1024>>>();
    k_scatter<<<(CAP * 4 + 255) / 256, 256>>>(deltas, anchors);
    k_mat    <<<MROW, 1024>>>();
    k_nms    <<<1, 1024, 8 * 32 * MW * 4>>>(out);
}